// round 1
// baseline (speedup 1.0000x reference)
#include <cuda_runtime.h>

#define BATCH  2
#define SLEN   2048
#define DMODEL 1024
#define NHEAD  16
#define DKH    64

// Scratch (allocation-free rule: __device__ globals)
__device__ float g_Q[BATCH * SLEN * DMODEL];
__device__ float g_K[BATCH * SLEN * DMODEL];
__device__ float g_V[BATCH * SLEN * DMODEL];
__device__ float g_A[BATCH * SLEN * DMODEL];

// C[M,N] = A[M,K] @ W[N,K]^T + bias[N]   (both K-major, "NT" GEMM)
// Tiles: 128(M) x 64(N) x 16(K), 256 threads, 8x4 per-thread register tile.
__global__ __launch_bounds__(256) void gemm_nt_bias(
    const float* __restrict__ A, const float* __restrict__ W,
    const float* __restrict__ bias, float* __restrict__ C,
    int M, int N, int K)
{
    __shared__ float As[16][128];
    __shared__ float Bs[16][64];

    const int tid = threadIdx.x;
    const int bm = blockIdx.y * 128;
    const int bn = blockIdx.x * 64;
    const int tx = tid & 15;   // N direction: 16 * 4 = 64
    const int ty = tid >> 4;   // M direction: 16 * 8 = 128

    float acc[8][4];
#pragma unroll
    for (int i = 0; i < 8; i++)
#pragma unroll
        for (int j = 0; j < 4; j++) acc[i][j] = 0.0f;

    const float* Ab = A + (size_t)bm * K;
    const float* Wb = W + (size_t)bn * K;

    for (int k0 = 0; k0 < K; k0 += 16) {
        // A tile: 128 rows x 16 cols = 512 float4, 2 per thread
#pragma unroll
        for (int i = 0; i < 2; i++) {
            int idx = tid + i * 256;
            int r = idx >> 2, c4 = idx & 3;
            float4 v = *(const float4*)(Ab + (size_t)r * K + k0 + c4 * 4);
            As[c4 * 4 + 0][r] = v.x; As[c4 * 4 + 1][r] = v.y;
            As[c4 * 4 + 2][r] = v.z; As[c4 * 4 + 3][r] = v.w;
        }
        // W tile: 64 rows x 16 cols = 256 float4, 1 per thread
        {
            int r = tid >> 2, c4 = tid & 3;
            float4 v = *(const float4*)(Wb + (size_t)r * K + k0 + c4 * 4);
            Bs[c4 * 4 + 0][r] = v.x; Bs[c4 * 4 + 1][r] = v.y;
            Bs[c4 * 4 + 2][r] = v.z; Bs[c4 * 4 + 3][r] = v.w;
        }
        __syncthreads();
#pragma unroll
        for (int k = 0; k < 16; k++) {
            float a[8], b[4];
            *(float4*)&a[0] = *(const float4*)&As[k][ty * 8];
            *(float4*)&a[4] = *(const float4*)&As[k][ty * 8 + 4];
            *(float4*)&b[0] = *(const float4*)&Bs[k][tx * 4];
#pragma unroll
            for (int i = 0; i < 8; i++)
#pragma unroll
                for (int j = 0; j < 4; j++)
                    acc[i][j] = fmaf(a[i], b[j], acc[i][j]);
        }
        __syncthreads();
    }

    float4 b4 = *(const float4*)&bias[bn + tx * 4];
#pragma unroll
    for (int i = 0; i < 8; i++) {
        float4 o;
        o.x = acc[i][0] + b4.x; o.y = acc[i][1] + b4.y;
        o.z = acc[i][2] + b4.z; o.w = acc[i][3] + b4.w;
        *(float4*)&C[(size_t)(bm + ty * 8 + i) * N + bn + tx * 4] = o;
    }
}

// Flash attention, fp32. CTA = 64 queries of one (b, h). 8 warps; warp w owns
// query rows w*8..w*8+7; lane owns key/val columns 2*lane, 2*lane+1.
// Online softmax; mask==0 -> exact -1e9f (matches reference bit pattern).
__global__ __launch_bounds__(256) void flash_attn(const int* __restrict__ mask)
{
    extern __shared__ float sm[];
    float* Qs = sm;                 // [64][64]
    float* Kt = Qs + 64 * 64;       // [64][68]  Kt[kk*68 + c] (transposed, padded)
    float* Vs = Kt + 64 * 68;       // [64][64]
    float* Ps = Vs + 64 * 64;       // [64][64]

    const int tid  = threadIdx.x;
    const int lane = tid & 31;
    const int w    = tid >> 5;
    const int q0   = blockIdx.x * 64;
    const int h    = blockIdx.y;
    const int b    = blockIdx.z;
    const int c0   = lane * 2;

    const size_t base = (size_t)b * SLEN * DMODEL + (size_t)h * DKH;

    // Load Q tile (64 x 64)
    for (int t = tid; t < 1024; t += 256) {
        int r = t >> 4, c4 = t & 15;
        *(float4*)&Qs[r * 64 + c4 * 4] =
            *(const float4*)&g_Q[base + (size_t)(q0 + r) * DMODEL + c4 * 4];
    }

    float m[8], l[8], acc[8][2];
#pragma unroll
    for (int r = 0; r < 8; r++) {
        m[r] = -1e30f; l[r] = 0.0f; acc[r][0] = 0.0f; acc[r][1] = 0.0f;
    }

    const int* mbase = mask + (size_t)b * SLEN * SLEN;

    for (int j = 0; j < SLEN; j += 64) {
        __syncthreads();  // protect Kt/Vs from prior-iteration readers (and Qs on iter 0)
        // Load K (transposed into Kt) and V tiles
        for (int t = tid; t < 1024; t += 256) {
            int r = t >> 4, c4 = t & 15;
            float4 kv = *(const float4*)&g_K[base + (size_t)(j + r) * DMODEL + c4 * 4];
            Kt[(c4 * 4 + 0) * 68 + r] = kv.x;
            Kt[(c4 * 4 + 1) * 68 + r] = kv.y;
            Kt[(c4 * 4 + 2) * 68 + r] = kv.z;
            Kt[(c4 * 4 + 3) * 68 + r] = kv.w;
            *(float4*)&Vs[r * 64 + c4 * 4] =
                *(const float4*)&g_V[base + (size_t)(j + r) * DMODEL + c4 * 4];
        }
        __syncthreads();

        // Scores: s[r][t] = Q[row r] . K[col c0+t]
        float s[8][2];
#pragma unroll
        for (int r = 0; r < 8; r++) { s[r][0] = 0.0f; s[r][1] = 0.0f; }

        for (int kk = 0; kk < 64; kk += 4) {
            float2 kv0 = *(const float2*)&Kt[(kk + 0) * 68 + c0];
            float2 kv1 = *(const float2*)&Kt[(kk + 1) * 68 + c0];
            float2 kv2 = *(const float2*)&Kt[(kk + 2) * 68 + c0];
            float2 kv3 = *(const float2*)&Kt[(kk + 3) * 68 + c0];
#pragma unroll
            for (int r = 0; r < 8; r++) {
                float4 q = *(const float4*)&Qs[(w * 8 + r) * 64 + kk];
                s[r][0] = fmaf(q.x, kv0.x, s[r][0]);
                s[r][0] = fmaf(q.y, kv1.x, s[r][0]);
                s[r][0] = fmaf(q.z, kv2.x, s[r][0]);
                s[r][0] = fmaf(q.w, kv3.x, s[r][0]);
                s[r][1] = fmaf(q.x, kv0.y, s[r][1]);
                s[r][1] = fmaf(q.y, kv1.y, s[r][1]);
                s[r][1] = fmaf(q.z, kv2.y, s[r][1]);
                s[r][1] = fmaf(q.w, kv3.y, s[r][1]);
            }
        }

        // Scale by 1/sqrt(64)=0.125, mask==0 -> -1e9 (exact, like reference)
#pragma unroll
        for (int r = 0; r < 8; r++) {
            int2 mk = *(const int2*)&mbase[(size_t)(q0 + w * 8 + r) * SLEN + j + c0];
            s[r][0] = mk.x ? s[r][0] * 0.125f : -1e9f;
            s[r][1] = mk.y ? s[r][1] * 0.125f : -1e9f;
        }

        // Online softmax update (per warp; all lanes hold identical m/l)
#pragma unroll
        for (int r = 0; r < 8; r++) {
            float v = fmaxf(s[r][0], s[r][1]);
#pragma unroll
            for (int o = 16; o > 0; o >>= 1)
                v = fmaxf(v, __shfl_xor_sync(0xffffffffu, v, o));
            float mn = fmaxf(m[r], v);
            float sc = __expf(m[r] - mn);
            float p0 = __expf(s[r][0] - mn);
            float p1 = __expf(s[r][1] - mn);
            float ls = p0 + p1;
#pragma unroll
            for (int o = 16; o > 0; o >>= 1)
                ls += __shfl_xor_sync(0xffffffffu, ls, o);
            l[r] = l[r] * sc + ls;
            m[r] = mn;
            acc[r][0] *= sc; acc[r][1] *= sc;
            Ps[(w * 8 + r) * 64 + c0]     = p0;
            Ps[(w * 8 + r) * 64 + c0 + 1] = p1;
        }
        __syncwarp();  // Ps rows are private to this warp

        // acc += P @ V
        for (int c = 0; c < 64; c += 4) {
            float2 v0 = *(const float2*)&Vs[(c + 0) * 64 + c0];
            float2 v1 = *(const float2*)&Vs[(c + 1) * 64 + c0];
            float2 v2 = *(const float2*)&Vs[(c + 2) * 64 + c0];
            float2 v3 = *(const float2*)&Vs[(c + 3) * 64 + c0];
#pragma unroll
            for (int r = 0; r < 8; r++) {
                float4 p = *(const float4*)&Ps[(w * 8 + r) * 64 + c];
                acc[r][0] = fmaf(p.x, v0.x, acc[r][0]);
                acc[r][0] = fmaf(p.y, v1.x, acc[r][0]);
                acc[r][0] = fmaf(p.z, v2.x, acc[r][0]);
                acc[r][0] = fmaf(p.w, v3.x, acc[r][0]);
                acc[r][1] = fmaf(p.x, v0.y, acc[r][1]);
                acc[r][1] = fmaf(p.y, v1.y, acc[r][1]);
                acc[r][1] = fmaf(p.z, v2.y, acc[r][1]);
                acc[r][1] = fmaf(p.w, v3.y, acc[r][1]);
            }
        }
    }

    // Normalize and write to the "concat heads" layout [B*S, D] at cols h*64..
#pragma unroll
    for (int r = 0; r < 8; r++) {
        float inv = 1.0f / l[r];
        float2 o = make_float2(acc[r][0] * inv, acc[r][1] * inv);
        *(float2*)&g_A[base + (size_t)(q0 + w * 8 + r) * DMODEL + c0] = o;
    }
}

extern "C" void kernel_launch(void* const* d_in, const int* in_sizes, int n_in,
                              void* d_out, int out_size)
{
    const float* query = (const float*)d_in[0];
    const float* key   = (const float*)d_in[1];
    const float* value = (const float*)d_in[2];
    const int*   mask  = (const int*)d_in[3];
    const float* Wq    = (const float*)d_in[4];
    const float* bq    = (const float*)d_in[5];
    const float* Wk    = (const float*)d_in[6];
    const float* bk    = (const float*)d_in[7];
    const float* Wv    = (const float*)d_in[8];
    const float* bv    = (const float*)d_in[9];
    const float* Wo    = (const float*)d_in[10];
    const float* bo    = (const float*)d_in[11];
    float* out = (float*)d_out;

    float *dQ, *dK, *dV, *dA;
    cudaGetSymbolAddress((void**)&dQ, g_Q);
    cudaGetSymbolAddress((void**)&dK, g_K);
    cudaGetSymbolAddress((void**)&dV, g_V);
    cudaGetSymbolAddress((void**)&dA, g_A);

    const int M = BATCH * SLEN;          // 4096
    dim3 gg(DMODEL / 64, M / 128);       // (16, 32)

    gemm_nt_bias<<<gg, 256>>>(query, Wq, bq, dQ, M, DMODEL, DMODEL);
    gemm_nt_bias<<<gg, 256>>>(key,   Wk, bk, dK, M, DMODEL, DMODEL);
    gemm_nt_bias<<<gg, 256>>>(value, Wv, bv, dV, M, DMODEL, DMODEL);

    size_t shmem = (size_t)(64 * 64 + 64 * 68 + 64 * 64 + 64 * 64) * sizeof(float); // 66560 B
    cudaFuncSetAttribute(flash_attn, cudaFuncAttributeMaxDynamicSharedMemorySize, (int)shmem);
    dim3 fg(SLEN / 64, NHEAD, BATCH);    // (32, 16, 2)
    flash_attn<<<fg, 256, shmem>>>(mask);

    gemm_nt_bias<<<gg, 256>>>(dA, Wo, bo, out, M, DMODEL, DMODEL);
}

// round 3
// speedup vs baseline: 1.4367x; 1.4367x over previous
#include <cuda_runtime.h>
#include <cuda_bf16.h>
#include <cstdint>

#define BATCH  2
#define SLEN   2048
#define DMODEL 1024
#define NHEAD  16
#define DKH    64
#define MROWS  (BATCH * SLEN)   // 4096

// ---------------- scratch (allocation-free rule: __device__ globals) --------
__device__ __align__(16) float g_Q[MROWS * DMODEL];
__device__ __align__(16) float g_K[MROWS * DMODEL];
__device__ __align__(16) float g_V[MROWS * DMODEL];
__device__ __align__(16) float g_A[MROWS * DMODEL];
__device__ __align__(16) __nv_bfloat16 g_xhi[MROWS * DMODEL];
__device__ __align__(16) __nv_bfloat16 g_xlo[MROWS * DMODEL];
__device__ __align__(16) __nv_bfloat16 g_whi[DMODEL * DMODEL];
__device__ __align__(16) __nv_bfloat16 g_wlo[DMODEL * DMODEL];

// ---------------- helpers ----------------------------------------------------
__device__ __forceinline__ uint32_t smem_u32(const void* p) {
    return (uint32_t)__cvta_generic_to_shared(p);
}
__device__ __forceinline__ void ldsm_x4(uint32_t (&r)[4], uint32_t addr) {
    asm volatile("ldmatrix.sync.aligned.m8n8.x4.shared.b16 {%0,%1,%2,%3}, [%4];"
                 : "=r"(r[0]), "=r"(r[1]), "=r"(r[2]), "=r"(r[3]) : "r"(addr));
}
__device__ __forceinline__ void mma_bf16(float (&d)[4], const uint32_t (&a)[4],
                                         uint32_t b0, uint32_t b1) {
    asm volatile("mma.sync.aligned.m16n8k16.row.col.f32.bf16.bf16.f32 "
                 "{%0,%1,%2,%3}, {%4,%5,%6,%7}, {%8,%9}, {%0,%1,%2,%3};"
                 : "+f"(d[0]), "+f"(d[1]), "+f"(d[2]), "+f"(d[3])
                 : "r"(a[0]), "r"(a[1]), "r"(a[2]), "r"(a[3]), "r"(b0), "r"(b1));
}

// ---------------- fp32 -> (hi, lo) bf16 split -------------------------------
__global__ __launch_bounds__(256) void split_f32(
    const float4* __restrict__ x, __nv_bfloat162* __restrict__ hi,
    __nv_bfloat162* __restrict__ lo, int n4)
{
    int i = blockIdx.x * blockDim.x + threadIdx.x;
    if (i >= n4) return;
    float4 v = x[i];
    __nv_bfloat16 h0 = __float2bfloat16(v.x);
    __nv_bfloat16 h1 = __float2bfloat16(v.y);
    __nv_bfloat16 h2 = __float2bfloat16(v.z);
    __nv_bfloat16 h3 = __float2bfloat16(v.w);
    __nv_bfloat16 l0 = __float2bfloat16(v.x - __bfloat162float(h0));
    __nv_bfloat16 l1 = __float2bfloat16(v.y - __bfloat162float(h1));
    __nv_bfloat16 l2 = __float2bfloat16(v.z - __bfloat162float(h2));
    __nv_bfloat16 l3 = __float2bfloat16(v.w - __bfloat162float(h3));
    hi[2 * i]     = __nv_bfloat162(h0, h1);
    hi[2 * i + 1] = __nv_bfloat162(h2, h3);
    lo[2 * i]     = __nv_bfloat162(l0, l1);
    lo[2 * i + 1] = __nv_bfloat162(l2, l3);
}

// ---------------- mma.sync GEMM: C[4096,1024] = X @ W^T + bias --------------
// CTA 128x128, K-chunk 64 (SW128-swizzled 128B rows), double-buffered cp.async.
// 8 warps = 2(M) x 4(N); warp tile 64x32; m16n8k16 bf16 HMMA, 3-term split.
#define KCH      64
#define NCHUNK   (DMODEL / KCH)   // 16
#define TILE_B   16384            // 128 rows x 128 bytes
#define STAGE_B  (4 * TILE_B)     // Ahi, Alo, Whi, Wlo
#define GEMM_SMEM (2 * STAGE_B)   // 131072

__global__ __launch_bounds__(256, 1) void gemm_mma(
    const __nv_bfloat16* __restrict__ xhi, const __nv_bfloat16* __restrict__ xlo,
    const __nv_bfloat16* __restrict__ whi, const __nv_bfloat16* __restrict__ wlo,
    const float* __restrict__ bias, float* __restrict__ C)
{
    extern __shared__ __align__(1024) char smem[];
    const uint32_t sb = smem_u32(smem);
    const int tid = threadIdx.x, wid = tid >> 5, lane = tid & 31;
    const int warp_m = wid >> 2;     // 0..1
    const int warp_n = wid & 3;      // 0..3
    const int bn = blockIdx.x * 128;
    const int bm = blockIdx.y * 128;

    float acc[4][4][4];
#pragma unroll
    for (int i = 0; i < 4; i++)
#pragma unroll
        for (int j = 0; j < 4; j++)
#pragma unroll
            for (int e = 0; e < 4; e++) acc[i][j][e] = 0.0f;

    const __nv_bfloat16* srcs[4] = {
        xhi + (size_t)bm * DMODEL, xlo + (size_t)bm * DMODEL,
        whi + (size_t)bn * DMODEL, wlo + (size_t)bn * DMODEL };

    auto load_chunk = [&](int chunk, int stage) {
        const int k0 = chunk * KCH;
        const uint32_t st = sb + stage * STAGE_B;
#pragma unroll
        for (int a = 0; a < 4; a++) {
            const __nv_bfloat16* src = srcs[a];
            const uint32_t tb = st + a * TILE_B;
#pragma unroll
            for (int i = 0; i < 4; i++) {
                int idx = tid + i * 256;          // 1024 x 16B
                int row = idx >> 3, c8 = idx & 7;
                uint32_t boff = row * 128 + c8 * 16;
                uint32_t sw = boff ^ ((boff >> 3) & 0x70);
                const void* g = src + (size_t)row * DMODEL + k0 + c8 * 8;
                asm volatile("cp.async.cg.shared.global [%0], [%1], 16;"
                             :: "r"(tb + sw), "l"(g));
            }
        }
        asm volatile("cp.async.commit_group;" ::: "memory");
    };

    load_chunk(0, 0);

    for (int i = 0; i < NCHUNK; i++) {
        if (i + 1 < NCHUNK) {
            load_chunk(i + 1, (i + 1) & 1);
            asm volatile("cp.async.wait_group 1;" ::: "memory");
        } else {
            asm volatile("cp.async.wait_group 0;" ::: "memory");
        }
        __syncthreads();

        const uint32_t st = sb + (i & 1) * STAGE_B;
#pragma unroll
        for (int ks = 0; ks < 4; ks++) {
            const int cb = ks * 32 + ((lane >> 4) << 4);  // byte col in 128B row
            uint32_t ah[4][4], al[4][4], wh[2][4], wl[2][4];
#pragma unroll
            for (int mi = 0; mi < 4; mi++) {
                int r = warp_m * 64 + mi * 16 + (lane & 15);
                uint32_t boff = r * 128 + cb;
                uint32_t sw = boff ^ ((boff >> 3) & 0x70);
                ldsm_x4(ah[mi], st + sw);
                ldsm_x4(al[mi], st + TILE_B + sw);
            }
#pragma unroll
            for (int np = 0; np < 2; np++) {
                int r = warp_n * 32 + np * 16 + (lane & 15);
                uint32_t boff = r * 128 + cb;
                uint32_t sw = boff ^ ((boff >> 3) & 0x70);
                ldsm_x4(wh[np], st + 2 * TILE_B + sw);
                ldsm_x4(wl[np], st + 3 * TILE_B + sw);
            }
#pragma unroll
            for (int mi = 0; mi < 4; mi++)
#pragma unroll
                for (int nj = 0; nj < 4; nj++) {
                    int np = nj >> 1, o = nj & 1;
                    mma_bf16(acc[mi][nj], ah[mi], wh[np][o], wh[np][o + 2]);
                    mma_bf16(acc[mi][nj], ah[mi], wl[np][o], wl[np][o + 2]);
                    mma_bf16(acc[mi][nj], al[mi], wh[np][o], wh[np][o + 2]);
                }
        }
        __syncthreads();
    }

    // Epilogue: frag (m16n8): thread holds (r0, c0),(r0, c0+1),(r0+8, ...)
    const int r0 = lane >> 2, c0 = (lane & 3) * 2;
#pragma unroll
    for (int mi = 0; mi < 4; mi++) {
#pragma unroll
        for (int nj = 0; nj < 4; nj++) {
            int row = bm + warp_m * 64 + mi * 16 + r0;
            int col = bn + warp_n * 32 + nj * 8 + c0;
            float2 b2 = *(const float2*)&bias[col];
            float2 o0 = make_float2(acc[mi][nj][0] + b2.x, acc[mi][nj][1] + b2.y);
            float2 o1 = make_float2(acc[mi][nj][2] + b2.x, acc[mi][nj][3] + b2.y);
            *(float2*)&C[(size_t)row * DMODEL + col] = o0;
            *(float2*)&C[(size_t)(row + 8) * DMODEL + col] = o1;
        }
    }
}

// ---------------- flash attention (unchanged R1, fp32) ----------------------
__global__ __launch_bounds__(256) void flash_attn(const int* __restrict__ mask)
{
    extern __shared__ float sm[];
    float* Qs = sm;                 // [64][64]
    float* Kt = Qs + 64 * 64;       // [64][68]
    float* Vs = Kt + 64 * 68;       // [64][64]
    float* Ps = Vs + 64 * 64;       // [64][64]

    const int tid  = threadIdx.x;
    const int lane = tid & 31;
    const int w    = tid >> 5;
    const int q0   = blockIdx.x * 64;
    const int h    = blockIdx.y;
    const int b    = blockIdx.z;
    const int c0   = lane * 2;

    const size_t base = (size_t)b * SLEN * DMODEL + (size_t)h * DKH;

    for (int t = tid; t < 1024; t += 256) {
        int r = t >> 4, c4 = t & 15;
        *(float4*)&Qs[r * 64 + c4 * 4] =
            *(const float4*)&g_Q[base + (size_t)(q0 + r) * DMODEL + c4 * 4];
    }

    float m[8], l[8], acc[8][2];
#pragma unroll
    for (int r = 0; r < 8; r++) {
        m[r] = -1e30f; l[r] = 0.0f; acc[r][0] = 0.0f; acc[r][1] = 0.0f;
    }

    const int* mbase = mask + (size_t)b * SLEN * SLEN;

    for (int j = 0; j < SLEN; j += 64) {
        __syncthreads();
        for (int t = tid; t < 1024; t += 256) {
            int r = t >> 4, c4 = t & 15;
            float4 kv = *(const float4*)&g_K[base + (size_t)(j + r) * DMODEL + c4 * 4];
            Kt[(c4 * 4 + 0) * 68 + r] = kv.x;
            Kt[(c4 * 4 + 1) * 68 + r] = kv.y;
            Kt[(c4 * 4 + 2) * 68 + r] = kv.z;
            Kt[(c4 * 4 + 3) * 68 + r] = kv.w;
            *(float4*)&Vs[r * 64 + c4 * 4] =
                *(const float4*)&g_V[base + (size_t)(j + r) * DMODEL + c4 * 4];
        }
        __syncthreads();

        float s[8][2];
#pragma unroll
        for (int r = 0; r < 8; r++) { s[r][0] = 0.0f; s[r][1] = 0.0f; }

        for (int kk = 0; kk < 64; kk += 4) {
            float2 kv0 = *(const float2*)&Kt[(kk + 0) * 68 + c0];
            float2 kv1 = *(const float2*)&Kt[(kk + 1) * 68 + c0];
            float2 kv2 = *(const float2*)&Kt[(kk + 2) * 68 + c0];
            float2 kv3 = *(const float2*)&Kt[(kk + 3) * 68 + c0];
#pragma unroll
            for (int r = 0; r < 8; r++) {
                float4 q = *(const float4*)&Qs[(w * 8 + r) * 64 + kk];
                s[r][0] = fmaf(q.x, kv0.x, s[r][0]);
                s[r][0] = fmaf(q.y, kv1.x, s[r][0]);
                s[r][0] = fmaf(q.z, kv2.x, s[r][0]);
                s[r][0] = fmaf(q.w, kv3.x, s[r][0]);
                s[r][1] = fmaf(q.x, kv0.y, s[r][1]);
                s[r][1] = fmaf(q.y, kv1.y, s[r][1]);
                s[r][1] = fmaf(q.z, kv2.y, s[r][1]);
                s[r][1] = fmaf(q.w, kv3.y, s[r][1]);
            }
        }

#pragma unroll
        for (int r = 0; r < 8; r++) {
            int2 mk = *(const int2*)&mbase[(size_t)(q0 + w * 8 + r) * SLEN + j + c0];
            s[r][0] = mk.x ? s[r][0] * 0.125f : -1e9f;
            s[r][1] = mk.y ? s[r][1] * 0.125f : -1e9f;
        }

#pragma unroll
        for (int r = 0; r < 8; r++) {
            float v = fmaxf(s[r][0], s[r][1]);
#pragma unroll
            for (int o = 16; o > 0; o >>= 1)
                v = fmaxf(v, __shfl_xor_sync(0xffffffffu, v, o));
            float mn = fmaxf(m[r], v);
            float sc = __expf(m[r] - mn);
            float p0 = __expf(s[r][0] - mn);
            float p1 = __expf(s[r][1] - mn);
            float ls = p0 + p1;
#pragma unroll
            for (int o = 16; o > 0; o >>= 1)
                ls += __shfl_xor_sync(0xffffffffu, ls, o);
            l[r] = l[r] * sc + ls;
            m[r] = mn;
            acc[r][0] *= sc; acc[r][1] *= sc;
            Ps[(w * 8 + r) * 64 + c0]     = p0;
            Ps[(w * 8 + r) * 64 + c0 + 1] = p1;
        }
        __syncwarp();

        for (int c = 0; c < 64; c += 4) {
            float2 v0 = *(const float2*)&Vs[(c + 0) * 64 + c0];
            float2 v1 = *(const float2*)&Vs[(c + 1) * 64 + c0];
            float2 v2 = *(const float2*)&Vs[(c + 2) * 64 + c0];
            float2 v3 = *(const float2*)&Vs[(c + 3) * 64 + c0];
#pragma unroll
            for (int r = 0; r < 8; r++) {
                float4 p = *(const float4*)&Ps[(w * 8 + r) * 64 + c];
                acc[r][0] = fmaf(p.x, v0.x, acc[r][0]);
                acc[r][0] = fmaf(p.y, v1.x, acc[r][0]);
                acc[r][0] = fmaf(p.z, v2.x, acc[r][0]);
                acc[r][0] = fmaf(p.w, v3.x, acc[r][0]);
                acc[r][1] = fmaf(p.x, v0.y, acc[r][1]);
                acc[r][1] = fmaf(p.y, v1.y, acc[r][1]);
                acc[r][1] = fmaf(p.z, v2.y, acc[r][1]);
                acc[r][1] = fmaf(p.w, v3.y, acc[r][1]);
            }
        }
    }

#pragma unroll
    for (int r = 0; r < 8; r++) {
        float inv = 1.0f / l[r];
        float2 o = make_float2(acc[r][0] * inv, acc[r][1] * inv);
        *(float2*)&g_A[base + (size_t)(q0 + w * 8 + r) * DMODEL + c0] = o;
    }
}

// ---------------- launcher ---------------------------------------------------
extern "C" void kernel_launch(void* const* d_in, const int* in_sizes, int n_in,
                              void* d_out, int out_size)
{
    const float* query = (const float*)d_in[0];
    const float* key   = (const float*)d_in[1];
    const float* value = (const float*)d_in[2];
    const int*   mask  = (const int*)d_in[3];
    const float* Wq    = (const float*)d_in[4];
    const float* bq    = (const float*)d_in[5];
    const float* Wk    = (const float*)d_in[6];
    const float* bk    = (const float*)d_in[7];
    const float* Wv    = (const float*)d_in[8];
    const float* bv    = (const float*)d_in[9];
    const float* Wo    = (const float*)d_in[10];
    const float* bo    = (const float*)d_in[11];
    float* out = (float*)d_out;

    float *dQ, *dK, *dV, *dA;
    __nv_bfloat16 *xhi, *xlo, *whi, *wlo;
    cudaGetSymbolAddress((void**)&dQ, g_Q);
    cudaGetSymbolAddress((void**)&dK, g_K);
    cudaGetSymbolAddress((void**)&dV, g_V);
    cudaGetSymbolAddress((void**)&dA, g_A);
    cudaGetSymbolAddress((void**)&xhi, g_xhi);
    cudaGetSymbolAddress((void**)&xlo, g_xlo);
    cudaGetSymbolAddress((void**)&whi, g_whi);
    cudaGetSymbolAddress((void**)&wlo, g_wlo);

    cudaFuncSetAttribute(gemm_mma, cudaFuncAttributeMaxDynamicSharedMemorySize, GEMM_SMEM);

    const int nx4 = MROWS * DMODEL / 4;   // 1048576
    const int nw4 = DMODEL * DMODEL / 4;  // 262144
    dim3 gg(DMODEL / 128, MROWS / 128);   // (8, 32)

    auto run_gemm = [&](const float* x, const float* W, const float* b, float* C) {
        split_f32<<<nx4 / 256, 256>>>((const float4*)x, (__nv_bfloat162*)xhi,
                                      (__nv_bfloat162*)xlo, nx4);
        split_f32<<<nw4 / 256, 256>>>((const float4*)W, (__nv_bfloat162*)whi,
                                      (__nv_bfloat162*)wlo, nw4);
        gemm_mma<<<gg, 256, GEMM_SMEM>>>(xhi, xlo, whi, wlo, b, C);
    };

    run_gemm(query, Wq, bq, dQ);
    run_gemm(key,   Wk, bk, dK);
    run_gemm(value, Wv, bv, dV);

    size_t shmem = (size_t)(64 * 64 + 64 * 68 + 64 * 64 + 64 * 64) * sizeof(float);
    cudaFuncSetAttribute(flash_attn, cudaFuncAttributeMaxDynamicSharedMemorySize, (int)shmem);
    dim3 fg(SLEN / 64, NHEAD, BATCH);
    flash_attn<<<fg, 256, shmem>>>(mask);

    run_gemm(dA, Wo, bo, out);
}

// round 4
// speedup vs baseline: 2.8362x; 1.9741x over previous
#include <cuda_runtime.h>
#include <cuda_bf16.h>
#include <cstdint>

#define BATCH  2
#define SLEN   2048
#define DMODEL 1024
#define NHEAD  16
#define DKH    64
#define MROWS  (BATCH * SLEN)   // 4096

// ---------------- scratch (allocation-free rule: __device__ globals) --------
__device__ __align__(16) __nv_bfloat16 g_xhi[MROWS * DMODEL];
__device__ __align__(16) __nv_bfloat16 g_xlo[MROWS * DMODEL];
__device__ __align__(16) __nv_bfloat16 g_qhi[MROWS * DMODEL];
__device__ __align__(16) __nv_bfloat16 g_qlo[MROWS * DMODEL];
__device__ __align__(16) __nv_bfloat16 g_khi[MROWS * DMODEL];
__device__ __align__(16) __nv_bfloat16 g_klo[MROWS * DMODEL];
__device__ __align__(16) __nv_bfloat16 g_vhi[MROWS * DMODEL];
__device__ __align__(16) __nv_bfloat16 g_vlo[MROWS * DMODEL];
__device__ __align__(16) __nv_bfloat16 g_ahi[MROWS * DMODEL];
__device__ __align__(16) __nv_bfloat16 g_alo[MROWS * DMODEL];
__device__ __align__(16) __nv_bfloat16 g_wh[4][DMODEL * DMODEL];
__device__ __align__(16) __nv_bfloat16 g_wl[4][DMODEL * DMODEL];
__device__ __align__(16) __nv_bfloat16 g_bias[(size_t)BATCH * SLEN * SLEN];

// ---------------- helpers ----------------------------------------------------
__device__ __forceinline__ uint32_t smem_u32(const void* p) {
    return (uint32_t)__cvta_generic_to_shared(p);
}
__device__ __forceinline__ void ldsm_x4(uint32_t (&r)[4], uint32_t addr) {
    asm volatile("ldmatrix.sync.aligned.m8n8.x4.shared.b16 {%0,%1,%2,%3}, [%4];"
                 : "=r"(r[0]), "=r"(r[1]), "=r"(r[2]), "=r"(r[3]) : "r"(addr));
}
__device__ __forceinline__ void ldsm_x4_t(uint32_t (&r)[4], uint32_t addr) {
    asm volatile("ldmatrix.sync.aligned.m8n8.x4.trans.shared.b16 {%0,%1,%2,%3}, [%4];"
                 : "=r"(r[0]), "=r"(r[1]), "=r"(r[2]), "=r"(r[3]) : "r"(addr));
}
__device__ __forceinline__ void mma_bf16(float (&d)[4], const uint32_t (&a)[4],
                                         uint32_t b0, uint32_t b1) {
    asm volatile("mma.sync.aligned.m16n8k16.row.col.f32.bf16.bf16.f32 "
                 "{%0,%1,%2,%3}, {%4,%5,%6,%7}, {%8,%9}, {%0,%1,%2,%3};"
                 : "+f"(d[0]), "+f"(d[1]), "+f"(d[2]), "+f"(d[3])
                 : "r"(a[0]), "r"(a[1]), "r"(a[2]), "r"(a[3]), "r"(b0), "r"(b1));
}
__device__ __forceinline__ uint32_t pack_hi(float f0, float f1, __nv_bfloat162& h2) {
    h2 = __floats2bfloat162_rn(f0, f1);
    return *(uint32_t*)&h2;
}
__device__ __forceinline__ uint32_t pack_lo(float f0, float f1, const __nv_bfloat162& h2) {
    __nv_bfloat162 l2 = __floats2bfloat162_rn(f0 - __bfloat162float(h2.x),
                                              f1 - __bfloat162float(h2.y));
    return *(uint32_t*)&l2;
}

// ---------------- fp32 -> (hi, lo) bf16 split -------------------------------
__global__ __launch_bounds__(256) void split_f32(
    const float4* __restrict__ x, __nv_bfloat162* __restrict__ hi,
    __nv_bfloat162* __restrict__ lo, int n4)
{
    int i = blockIdx.x * blockDim.x + threadIdx.x;
    if (i >= n4) return;
    float4 v = x[i];
    __nv_bfloat162 h0, h1;
    uint32_t u0 = pack_hi(v.x, v.y, h0), u1 = pack_hi(v.z, v.w, h1);
    uint32_t l0 = pack_lo(v.x, v.y, h0), l1 = pack_lo(v.z, v.w, h1);
    *(uint32_t*)&hi[2 * i] = u0; *(uint32_t*)&hi[2 * i + 1] = u1;
    *(uint32_t*)&lo[2 * i] = l0; *(uint32_t*)&lo[2 * i + 1] = l1;
}

// ---------------- mask (int) -> additive bf16 bias --------------------------
__global__ __launch_bounds__(256) void mask_to_bias(
    const int4* __restrict__ mk, __nv_bfloat162* __restrict__ out, int n4)
{
    int i = blockIdx.x * blockDim.x + threadIdx.x;
    if (i >= n4) return;
    int4 m = mk[i];
    out[2 * i]     = __floats2bfloat162_rn(m.x ? 0.f : -1e9f, m.y ? 0.f : -1e9f);
    out[2 * i + 1] = __floats2bfloat162_rn(m.z ? 0.f : -1e9f, m.w ? 0.f : -1e9f);
}

// ---------------- mma.sync GEMM: C = X @ W^T + bias -------------------------
// CTA 128x128, K-chunk 64 swizzled, double-buffered cp.async; 3-term split.
// Epilogue: fp32 C (Chi==null) OR scaled bf16 hi/lo pair (Chi!=null).
#define KCH      64
#define NCHUNK   (DMODEL / KCH)
#define TILE_B   16384
#define STAGE_B  (4 * TILE_B)
#define GEMM_SMEM (2 * STAGE_B)

__global__ __launch_bounds__(256, 1) void gemm_mma(
    const __nv_bfloat16* __restrict__ xhi, const __nv_bfloat16* __restrict__ xlo,
    const __nv_bfloat16* __restrict__ whi, const __nv_bfloat16* __restrict__ wlo,
    const float* __restrict__ bias, float* __restrict__ C,
    __nv_bfloat16* __restrict__ Chi, __nv_bfloat16* __restrict__ Clo, float scale)
{
    extern __shared__ __align__(1024) char smem[];
    const uint32_t sb = smem_u32(smem);
    const int tid = threadIdx.x, wid = tid >> 5, lane = tid & 31;
    const int warp_m = wid >> 2, warp_n = wid & 3;
    const int bn = blockIdx.x * 128, bm = blockIdx.y * 128;

    float acc[4][4][4];
#pragma unroll
    for (int i = 0; i < 4; i++)
#pragma unroll
        for (int j = 0; j < 4; j++)
#pragma unroll
            for (int e = 0; e < 4; e++) acc[i][j][e] = 0.0f;

    const __nv_bfloat16* srcs[4] = {
        xhi + (size_t)bm * DMODEL, xlo + (size_t)bm * DMODEL,
        whi + (size_t)bn * DMODEL, wlo + (size_t)bn * DMODEL };

    auto load_chunk = [&](int chunk, int stage) {
        const int k0 = chunk * KCH;
        const uint32_t st = sb + stage * STAGE_B;
#pragma unroll
        for (int a = 0; a < 4; a++) {
            const __nv_bfloat16* src = srcs[a];
            const uint32_t tb = st + a * TILE_B;
#pragma unroll
            for (int i = 0; i < 4; i++) {
                int idx = tid + i * 256;
                int row = idx >> 3, c8 = idx & 7;
                uint32_t boff = row * 128 + c8 * 16;
                uint32_t sw = boff ^ ((boff >> 3) & 0x70);
                const void* g = src + (size_t)row * DMODEL + k0 + c8 * 8;
                asm volatile("cp.async.cg.shared.global [%0], [%1], 16;"
                             :: "r"(tb + sw), "l"(g));
            }
        }
        asm volatile("cp.async.commit_group;" ::: "memory");
    };

    load_chunk(0, 0);

    for (int i = 0; i < NCHUNK; i++) {
        if (i + 1 < NCHUNK) {
            load_chunk(i + 1, (i + 1) & 1);
            asm volatile("cp.async.wait_group 1;" ::: "memory");
        } else {
            asm volatile("cp.async.wait_group 0;" ::: "memory");
        }
        __syncthreads();

        const uint32_t st = sb + (i & 1) * STAGE_B;
#pragma unroll
        for (int ks = 0; ks < 4; ks++) {
            const int cb = ks * 32 + ((lane >> 4) << 4);
            uint32_t ah[4][4], al[4][4], wh[2][4], wl[2][4];
#pragma unroll
            for (int mi = 0; mi < 4; mi++) {
                int r = warp_m * 64 + mi * 16 + (lane & 15);
                uint32_t boff = r * 128 + cb;
                uint32_t sw = boff ^ ((boff >> 3) & 0x70);
                ldsm_x4(ah[mi], st + sw);
                ldsm_x4(al[mi], st + TILE_B + sw);
            }
#pragma unroll
            for (int np = 0; np < 2; np++) {
                int r = warp_n * 32 + np * 16 + (lane & 15);
                uint32_t boff = r * 128 + cb;
                uint32_t sw = boff ^ ((boff >> 3) & 0x70);
                ldsm_x4(wh[np], st + 2 * TILE_B + sw);
                ldsm_x4(wl[np], st + 3 * TILE_B + sw);
            }
#pragma unroll
            for (int mi = 0; mi < 4; mi++)
#pragma unroll
                for (int nj = 0; nj < 4; nj++) {
                    int np = nj >> 1, o = nj & 1;
                    mma_bf16(acc[mi][nj], ah[mi], wh[np][o], wh[np][o + 2]);
                    mma_bf16(acc[mi][nj], ah[mi], wl[np][o], wl[np][o + 2]);
                    mma_bf16(acc[mi][nj], al[mi], wh[np][o], wh[np][o + 2]);
                }
        }
        __syncthreads();
    }

    const int r0 = lane >> 2, c0 = (lane & 3) * 2;
#pragma unroll
    for (int mi = 0; mi < 4; mi++) {
#pragma unroll
        for (int nj = 0; nj < 4; nj++) {
            int row = bm + warp_m * 64 + mi * 16 + r0;
            int col = bn + warp_n * 32 + nj * 8 + c0;
            float2 b2 = *(const float2*)&bias[col];
            float v0 = (acc[mi][nj][0] + b2.x) * scale;
            float v1 = (acc[mi][nj][1] + b2.y) * scale;
            float v2 = (acc[mi][nj][2] + b2.x) * scale;
            float v3 = (acc[mi][nj][3] + b2.y) * scale;
            if (Chi) {
                __nv_bfloat162 h0, h1;
                uint32_t u0 = pack_hi(v0, v1, h0), u1 = pack_hi(v2, v3, h1);
                uint32_t l0 = pack_lo(v0, v1, h0), l1 = pack_lo(v2, v3, h1);
                *(uint32_t*)&Chi[(size_t)row * DMODEL + col] = u0;
                *(uint32_t*)&Clo[(size_t)row * DMODEL + col] = l0;
                *(uint32_t*)&Chi[(size_t)(row + 8) * DMODEL + col] = u1;
                *(uint32_t*)&Clo[(size_t)(row + 8) * DMODEL + col] = l1;
            } else {
                *(float2*)&C[(size_t)row * DMODEL + col] = make_float2(v0, v1);
                *(float2*)&C[(size_t)(row + 8) * DMODEL + col] = make_float2(v2, v3);
            }
        }
    }
}

// ---------------- flash attention on mma.sync -------------------------------
// CTA = 128 queries x one (b,h); 8 warps x m16. Bc=64 keys, double-buffered.
// QK^T: 3-term split; PV: scores->A-frag register reuse, split P, trans-ldmatrix V.
#define FA_STAGE 32768   // Khi, Klo, Vhi, Vlo tiles of 8KB each
#define FA_SMEM  (2 * FA_STAGE)

__global__ __launch_bounds__(256, 1) void flash_attn_mma(
    const __nv_bfloat16* __restrict__ Qhi, const __nv_bfloat16* __restrict__ Qlo,
    const __nv_bfloat16* __restrict__ Khi, const __nv_bfloat16* __restrict__ Klo,
    const __nv_bfloat16* __restrict__ Vhi, const __nv_bfloat16* __restrict__ Vlo,
    const __nv_bfloat16* __restrict__ bias,
    __nv_bfloat16* __restrict__ Ahi, __nv_bfloat16* __restrict__ Alo)
{
    extern __shared__ __align__(1024) char smem[];
    const uint32_t sb = smem_u32(smem);
    const int tid = threadIdx.x, wid = tid >> 5, lane = tid & 31;
    const int q0 = blockIdx.x * 128, h = blockIdx.y, b = blockIdx.z;

    const size_t tok0 = (size_t)b * SLEN;
    const size_t hoff = (size_t)h * DKH;
    const int qr = q0 + wid * 16 + (lane >> 2);

    // Q fragments (A-frags over d), 4 k16 steps, hi/lo
    uint32_t qh[4][4], ql[4][4];
    {
        const size_t b0 = (tok0 + qr) * DMODEL + hoff;
        const size_t b1 = (tok0 + qr + 8) * DMODEL + hoff;
#pragma unroll
        for (int t = 0; t < 4; t++) {
            int c = t * 16 + 2 * (lane & 3);
            qh[t][0] = *(const uint32_t*)&Qhi[b0 + c];
            qh[t][1] = *(const uint32_t*)&Qhi[b1 + c];
            qh[t][2] = *(const uint32_t*)&Qhi[b0 + c + 8];
            qh[t][3] = *(const uint32_t*)&Qhi[b1 + c + 8];
            ql[t][0] = *(const uint32_t*)&Qlo[b0 + c];
            ql[t][1] = *(const uint32_t*)&Qlo[b1 + c];
            ql[t][2] = *(const uint32_t*)&Qlo[b0 + c + 8];
            ql[t][3] = *(const uint32_t*)&Qlo[b1 + c + 8];
        }
    }

    const __nv_bfloat16* srcs[4] = {
        Khi + tok0 * DMODEL + hoff, Klo + tok0 * DMODEL + hoff,
        Vhi + tok0 * DMODEL + hoff, Vlo + tok0 * DMODEL + hoff };

    auto load_kv = [&](int blk, int stage) {
        const int k0 = blk * 64;
        const uint32_t st = sb + stage * FA_STAGE;
#pragma unroll
        for (int i = 0; i < 8; i++) {
            int idx = tid + i * 256;
            int a = idx >> 9, r = (idx >> 3) & 63, c8 = idx & 7;
            uint32_t boff = r * 128 + c8 * 16;
            uint32_t sw = boff ^ ((boff >> 3) & 0x70);
            const void* g = srcs[a] + (size_t)(k0 + r) * DMODEL + c8 * 8;
            asm volatile("cp.async.cg.shared.global [%0], [%1], 16;"
                         :: "r"(st + a * 8192 + sw), "l"(g));
        }
        asm volatile("cp.async.commit_group;" ::: "memory");
    };

    float m[2] = { -1e30f, -1e30f }, l[2] = { 0.f, 0.f };
    float o[8][4];
#pragma unroll
    for (int j = 0; j < 8; j++)
#pragma unroll
        for (int e = 0; e < 4; e++) o[j][e] = 0.f;

    const size_t brow = ((size_t)b * SLEN + qr) * SLEN;

    load_kv(0, 0);

    for (int blk = 0; blk < SLEN / 64; blk++) {
        if (blk + 1 < SLEN / 64) {
            load_kv(blk + 1, (blk + 1) & 1);
            asm volatile("cp.async.wait_group 1;" ::: "memory");
        } else {
            asm volatile("cp.async.wait_group 0;" ::: "memory");
        }
        __syncthreads();
        const uint32_t st = sb + (blk & 1) * FA_STAGE;

        // ---- scores S = (Q/8) K^T (+ mask bias) ----
        float S[8][4];
#pragma unroll
        for (int j = 0; j < 8; j++)
#pragma unroll
            for (int e = 0; e < 4; e++) S[j][e] = 0.f;

#pragma unroll
        for (int t = 0; t < 4; t++) {
            const int cb = t * 32 + ((lane >> 4) << 4);
#pragma unroll
            for (int np = 0; np < 4; np++) {
                int r = np * 16 + (lane & 15);
                uint32_t boff = r * 128 + cb;
                uint32_t sw = boff ^ ((boff >> 3) & 0x70);
                uint32_t kh[4], kl[4];
                ldsm_x4(kh, st + sw);
                ldsm_x4(kl, st + 8192 + sw);
#pragma unroll
                for (int o2 = 0; o2 < 2; o2++) {
                    int j = np * 2 + o2;
                    mma_bf16(S[j], qh[t], kh[o2], kh[o2 + 2]);
                    mma_bf16(S[j], qh[t], kl[o2], kl[o2 + 2]);
                    mma_bf16(S[j], ql[t], kh[o2], kh[o2 + 2]);
                }
            }
        }
#pragma unroll
        for (int j = 0; j < 8; j++) {
            int col = blk * 64 + j * 8 + 2 * (lane & 3);
            __nv_bfloat162 m0 = *(const __nv_bfloat162*)&bias[brow + col];
            __nv_bfloat162 m1 = *(const __nv_bfloat162*)&bias[brow + (size_t)8 * SLEN + col];
            S[j][0] += __low2float(m0); S[j][1] += __high2float(m0);
            S[j][2] += __low2float(m1); S[j][3] += __high2float(m1);
        }

        // ---- online softmax (per row-half) ----
#pragma unroll
        for (int hh = 0; hh < 2; hh++) {
            float mx = -1e30f;
#pragma unroll
            for (int j = 0; j < 8; j++)
                mx = fmaxf(mx, fmaxf(S[j][2 * hh], S[j][2 * hh + 1]));
            mx = fmaxf(mx, __shfl_xor_sync(0xffffffffu, mx, 1));
            mx = fmaxf(mx, __shfl_xor_sync(0xffffffffu, mx, 2));
            float mn = fmaxf(m[hh], mx);
            float sc = __expf(m[hh] - mn);
            m[hh] = mn;
            float sum = 0.f;
#pragma unroll
            for (int j = 0; j < 8; j++) {
                S[j][2 * hh]     = __expf(S[j][2 * hh]     - mn);
                S[j][2 * hh + 1] = __expf(S[j][2 * hh + 1] - mn);
                sum += S[j][2 * hh] + S[j][2 * hh + 1];
            }
            sum += __shfl_xor_sync(0xffffffffu, sum, 1);
            sum += __shfl_xor_sync(0xffffffffu, sum, 2);
            l[hh] = l[hh] * sc + sum;
#pragma unroll
            for (int j = 0; j < 8; j++) { o[j][2 * hh] *= sc; o[j][2 * hh + 1] *= sc; }
        }

        // ---- O += P V  (P from score frags, split hi/lo in registers) ----
#pragma unroll
        for (int t = 0; t < 4; t++) {
            uint32_t ph[4], pl[4];
            {
                __nv_bfloat162 h2;
                ph[0] = pack_hi(S[2 * t][0], S[2 * t][1], h2);
                pl[0] = pack_lo(S[2 * t][0], S[2 * t][1], h2);
                ph[1] = pack_hi(S[2 * t][2], S[2 * t][3], h2);
                pl[1] = pack_lo(S[2 * t][2], S[2 * t][3], h2);
                ph[2] = pack_hi(S[2 * t + 1][0], S[2 * t + 1][1], h2);
                pl[2] = pack_lo(S[2 * t + 1][0], S[2 * t + 1][1], h2);
                ph[3] = pack_hi(S[2 * t + 1][2], S[2 * t + 1][3], h2);
                pl[3] = pack_lo(S[2 * t + 1][2], S[2 * t + 1][3], h2);
            }
            const int vkey = t * 16 + ((lane >> 3) & 1) * 8 + (lane & 7);
#pragma unroll
            for (int g = 0; g < 4; g++) {
                int dcol = g * 16 + ((lane >> 4) & 1) * 8;
                uint32_t boff = vkey * 128 + dcol * 2;
                uint32_t sw = boff ^ ((boff >> 3) & 0x70);
                uint32_t vh[4], vl[4];
                ldsm_x4_t(vh, st + 16384 + sw);
                ldsm_x4_t(vl, st + 24576 + sw);
#pragma unroll
                for (int o2 = 0; o2 < 2; o2++) {
                    int j = g * 2 + o2;
                    mma_bf16(o[j], ph, vh[o2 * 2], vh[o2 * 2 + 1]);
                    mma_bf16(o[j], ph, vl[o2 * 2], vl[o2 * 2 + 1]);
                    mma_bf16(o[j], pl, vh[o2 * 2], vh[o2 * 2 + 1]);
                }
            }
        }
        __syncthreads();   // stage fully consumed before next-iter load overwrites
    }

    // ---- epilogue: normalize, write A as bf16 hi/lo ----
    const float i0 = 1.f / l[0], i1 = 1.f / l[1];
#pragma unroll
    for (int j = 0; j < 8; j++) {
        int c = j * 8 + 2 * (lane & 3);
        size_t a0 = (tok0 + qr) * DMODEL + hoff + c;
        size_t a1 = (tok0 + qr + 8) * DMODEL + hoff + c;
        __nv_bfloat162 h2;
        float f0 = o[j][0] * i0, f1 = o[j][1] * i0;
        uint32_t u = pack_hi(f0, f1, h2), v = pack_lo(f0, f1, h2);
        *(uint32_t*)&Ahi[a0] = u; *(uint32_t*)&Alo[a0] = v;
        f0 = o[j][2] * i1; f1 = o[j][3] * i1;
        u = pack_hi(f0, f1, h2); v = pack_lo(f0, f1, h2);
        *(uint32_t*)&Ahi[a1] = u; *(uint32_t*)&Alo[a1] = v;
    }
}

// ---------------- launcher ---------------------------------------------------
extern "C" void kernel_launch(void* const* d_in, const int* in_sizes, int n_in,
                              void* d_out, int out_size)
{
    const float* query = (const float*)d_in[0];
    const float* key   = (const float*)d_in[1];
    const float* value = (const float*)d_in[2];
    const int*   mask  = (const int*)d_in[3];
    const float* Wq    = (const float*)d_in[4];
    const float* bq    = (const float*)d_in[5];
    const float* Wk    = (const float*)d_in[6];
    const float* bk    = (const float*)d_in[7];
    const float* Wv    = (const float*)d_in[8];
    const float* bv    = (const float*)d_in[9];
    const float* Wo    = (const float*)d_in[10];
    const float* bo    = (const float*)d_in[11];
    float* out = (float*)d_out;

    __nv_bfloat16 *xhi, *xlo, *qhi, *qlo, *khi, *klo, *vhi, *vlo, *ahi, *alo, *bb;
    __nv_bfloat16 *wh[4], *wl[4];
    cudaGetSymbolAddress((void**)&xhi, g_xhi);
    cudaGetSymbolAddress((void**)&xlo, g_xlo);
    cudaGetSymbolAddress((void**)&qhi, g_qhi);
    cudaGetSymbolAddress((void**)&qlo, g_qlo);
    cudaGetSymbolAddress((void**)&khi, g_khi);
    cudaGetSymbolAddress((void**)&klo, g_klo);
    cudaGetSymbolAddress((void**)&vhi, g_vhi);
    cudaGetSymbolAddress((void**)&vlo, g_vlo);
    cudaGetSymbolAddress((void**)&ahi, g_ahi);
    cudaGetSymbolAddress((void**)&alo, g_alo);
    cudaGetSymbolAddress((void**)&bb,  g_bias);
    {
        __nv_bfloat16 *p;
        cudaGetSymbolAddress((void**)&p, g_wh);
        for (int i = 0; i < 4; i++) wh[i] = p + (size_t)i * DMODEL * DMODEL;
        cudaGetSymbolAddress((void**)&p, g_wl);
        for (int i = 0; i < 4; i++) wl[i] = p + (size_t)i * DMODEL * DMODEL;
    }

    cudaFuncSetAttribute(gemm_mma, cudaFuncAttributeMaxDynamicSharedMemorySize, GEMM_SMEM);
    cudaFuncSetAttribute(flash_attn_mma, cudaFuncAttributeMaxDynamicSharedMemorySize, FA_SMEM);

    const int nx4 = MROWS * DMODEL / 4;
    const int nw4 = DMODEL * DMODEL / 4;
    const int nb4 = BATCH * SLEN * SLEN / 4;   // 2097152
    dim3 gg(DMODEL / 128, MROWS / 128);

    // mask -> additive bf16 bias (overlaps nothing; cheap)
    mask_to_bias<<<nb4 / 256, 256>>>((const int4*)mask, (__nv_bfloat162*)bb, nb4);

    // weight splits
    const float* Ws[4] = { Wq, Wk, Wv, Wo };
    for (int i = 0; i < 4; i++)
        split_f32<<<nw4 / 256, 256>>>((const float4*)Ws[i], (__nv_bfloat162*)wh[i],
                                      (__nv_bfloat162*)wl[i], nw4);

    // projections -> bf16 hi/lo directly (scale folds 1/sqrt(dk) into Q)
    split_f32<<<nx4 / 256, 256>>>((const float4*)query, (__nv_bfloat162*)xhi,
                                  (__nv_bfloat162*)xlo, nx4);
    gemm_mma<<<gg, 256, GEMM_SMEM>>>(xhi, xlo, wh[0], wl[0], bq, nullptr, qhi, qlo, 0.125f);

    split_f32<<<nx4 / 256, 256>>>((const float4*)key, (__nv_bfloat162*)xhi,
                                  (__nv_bfloat162*)xlo, nx4);
    gemm_mma<<<gg, 256, GEMM_SMEM>>>(xhi, xlo, wh[1], wl[1], bk, nullptr, khi, klo, 1.f);

    split_f32<<<nx4 / 256, 256>>>((const float4*)value, (__nv_bfloat162*)xhi,
                                  (__nv_bfloat162*)xlo, nx4);
    gemm_mma<<<gg, 256, GEMM_SMEM>>>(xhi, xlo, wh[2], wl[2], bv, nullptr, vhi, vlo, 1.f);

    // fused attention (writes hi/lo for the O-GEMM)
    dim3 fg(SLEN / 128, NHEAD, BATCH);   // (16, 16, 2)
    flash_attn_mma<<<fg, 256, FA_SMEM>>>(qhi, qlo, khi, klo, vhi, vlo, bb, ahi, alo);

    // output projection, fp32 out
    gemm_mma<<<gg, 256, GEMM_SMEM>>>(ahi, alo, wh[3], wl[3], bo, out, nullptr, nullptr, 1.f);
}

// round 6
// speedup vs baseline: 3.1826x; 1.1221x over previous
#include <cuda_runtime.h>
#include <cuda_bf16.h>
#include <cstdint>

#define BATCH  2
#define SLEN   2048
#define DMODEL 1024
#define NHEAD  16
#define DKH    64
#define MROWS  (BATCH * SLEN)   // 4096

// ---------------- scratch (allocation-free rule: __device__ globals) --------
__device__ __align__(16) __nv_bfloat16 g_xhi[MROWS * DMODEL];
__device__ __align__(16) __nv_bfloat16 g_xlo[MROWS * DMODEL];
__device__ __align__(16) __nv_bfloat16 g_qhi[MROWS * DMODEL];
__device__ __align__(16) __nv_bfloat16 g_qlo[MROWS * DMODEL];
__device__ __align__(16) __nv_bfloat16 g_khi[MROWS * DMODEL];
__device__ __align__(16) __nv_bfloat16 g_klo[MROWS * DMODEL];
__device__ __align__(16) __nv_bfloat16 g_vhi[MROWS * DMODEL];
__device__ __align__(16) __nv_bfloat16 g_vlo[MROWS * DMODEL];
__device__ __align__(16) __nv_bfloat16 g_ahi[MROWS * DMODEL];
__device__ __align__(16) __nv_bfloat16 g_alo[MROWS * DMODEL];
__device__ __align__(16) __nv_bfloat16 g_wh[4][DMODEL * DMODEL];
__device__ __align__(16) __nv_bfloat16 g_wl[4][DMODEL * DMODEL];
__device__ __align__(16) __nv_bfloat16 g_bias[(size_t)BATCH * SLEN * SLEN];

// ---------------- helpers ----------------------------------------------------
__device__ __forceinline__ uint32_t smem_u32(const void* p) {
    return (uint32_t)__cvta_generic_to_shared(p);
}
__device__ __forceinline__ void ldsm_x4(uint32_t (&r)[4], uint32_t addr) {
    asm volatile("ldmatrix.sync.aligned.m8n8.x4.shared.b16 {%0,%1,%2,%3}, [%4];"
                 : "=r"(r[0]), "=r"(r[1]), "=r"(r[2]), "=r"(r[3]) : "r"(addr));
}
__device__ __forceinline__ void ldsm_x4_t(uint32_t (&r)[4], uint32_t addr) {
    asm volatile("ldmatrix.sync.aligned.m8n8.x4.trans.shared.b16 {%0,%1,%2,%3}, [%4];"
                 : "=r"(r[0]), "=r"(r[1]), "=r"(r[2]), "=r"(r[3]) : "r"(addr));
}
__device__ __forceinline__ void mma_bf16(float (&d)[4], const uint32_t (&a)[4],
                                         uint32_t b0, uint32_t b1) {
    asm volatile("mma.sync.aligned.m16n8k16.row.col.f32.bf16.bf16.f32 "
                 "{%0,%1,%2,%3}, {%4,%5,%6,%7}, {%8,%9}, {%0,%1,%2,%3};"
                 : "+f"(d[0]), "+f"(d[1]), "+f"(d[2]), "+f"(d[3])
                 : "r"(a[0]), "r"(a[1]), "r"(a[2]), "r"(a[3]), "r"(b0), "r"(b1));
}
__device__ __forceinline__ float ex2(float x) {
    float y;
    asm("ex2.approx.ftz.f32 %0, %1;" : "=f"(y) : "f"(x));
    return y;
}
__device__ __forceinline__ uint32_t pack_hi(float f0, float f1, __nv_bfloat162& h2) {
    h2 = __floats2bfloat162_rn(f0, f1);
    return *(uint32_t*)&h2;
}
__device__ __forceinline__ uint32_t pack_lo(float f0, float f1, const __nv_bfloat162& h2) {
    __nv_bfloat162 l2 = __floats2bfloat162_rn(f0 - __bfloat162float(h2.x),
                                              f1 - __bfloat162float(h2.y));
    return *(uint32_t*)&l2;
}

// ---------------- fp32 -> (hi, lo) bf16 split -------------------------------
__global__ __launch_bounds__(256) void split_f32(
    const float4* __restrict__ x, __nv_bfloat162* __restrict__ hi,
    __nv_bfloat162* __restrict__ lo, int n4)
{
    int i = blockIdx.x * blockDim.x + threadIdx.x;
    if (i >= n4) return;
    float4 v = x[i];
    __nv_bfloat162 h0, h1;
    uint32_t u0 = pack_hi(v.x, v.y, h0), u1 = pack_hi(v.z, v.w, h1);
    uint32_t l0 = pack_lo(v.x, v.y, h0), l1 = pack_lo(v.z, v.w, h1);
    *(uint32_t*)&hi[2 * i] = u0; *(uint32_t*)&hi[2 * i + 1] = u1;
    *(uint32_t*)&lo[2 * i] = l0; *(uint32_t*)&lo[2 * i + 1] = l1;
}

// ---------------- mask (int) -> additive bf16 bias --------------------------
__global__ __launch_bounds__(256) void mask_to_bias(
    const int4* __restrict__ mk, __nv_bfloat162* __restrict__ out, int n4)
{
    int i = blockIdx.x * blockDim.x + threadIdx.x;
    if (i >= n4) return;
    int4 m = mk[i];
    out[2 * i]     = __floats2bfloat162_rn(m.x ? 0.f : -1e9f, m.y ? 0.f : -1e9f);
    out[2 * i + 1] = __floats2bfloat162_rn(m.z ? 0.f : -1e9f, m.w ? 0.f : -1e9f);
}

// ---------------- mma.sync GEMM: C = X @ W^T + bias -------------------------
#define KCH      64
#define NCHUNK   (DMODEL / KCH)
#define TILE_B   16384
#define STAGE_B  (4 * TILE_B)
#define GEMM_SMEM (2 * STAGE_B)

__global__ __launch_bounds__(256, 1) void gemm_mma(
    const __nv_bfloat16* __restrict__ xhi, const __nv_bfloat16* __restrict__ xlo,
    const __nv_bfloat16* __restrict__ whi, const __nv_bfloat16* __restrict__ wlo,
    const float* __restrict__ bias, float* __restrict__ C,
    __nv_bfloat16* __restrict__ Chi, __nv_bfloat16* __restrict__ Clo, float scale)
{
    extern __shared__ __align__(1024) char smem[];
    const uint32_t sb = smem_u32(smem);
    const int tid = threadIdx.x, wid = tid >> 5, lane = tid & 31;
    const int warp_m = wid >> 2, warp_n = wid & 3;
    const int bn = blockIdx.x * 128, bm = blockIdx.y * 128;

    float acc[4][4][4];
#pragma unroll
    for (int i = 0; i < 4; i++)
#pragma unroll
        for (int j = 0; j < 4; j++)
#pragma unroll
            for (int e = 0; e < 4; e++) acc[i][j][e] = 0.0f;

    const __nv_bfloat16* srcs[4] = {
        xhi + (size_t)bm * DMODEL, xlo + (size_t)bm * DMODEL,
        whi + (size_t)bn * DMODEL, wlo + (size_t)bn * DMODEL };

    auto load_chunk = [&](int chunk, int stage) {
        const int k0 = chunk * KCH;
        const uint32_t st = sb + stage * STAGE_B;
#pragma unroll
        for (int a = 0; a < 4; a++) {
            const __nv_bfloat16* src = srcs[a];
            const uint32_t tb = st + a * TILE_B;
#pragma unroll
            for (int i = 0; i < 4; i++) {
                int idx = tid + i * 256;
                int row = idx >> 3, c8 = idx & 7;
                uint32_t boff = row * 128 + c8 * 16;
                uint32_t sw = boff ^ ((boff >> 3) & 0x70);
                const void* g = src + (size_t)row * DMODEL + k0 + c8 * 8;
                asm volatile("cp.async.cg.shared.global [%0], [%1], 16;"
                             :: "r"(tb + sw), "l"(g));
            }
        }
        asm volatile("cp.async.commit_group;" ::: "memory");
    };

    load_chunk(0, 0);

    for (int i = 0; i < NCHUNK; i++) {
        if (i + 1 < NCHUNK) {
            load_chunk(i + 1, (i + 1) & 1);
            asm volatile("cp.async.wait_group 1;" ::: "memory");
        } else {
            asm volatile("cp.async.wait_group 0;" ::: "memory");
        }
        __syncthreads();

        const uint32_t st = sb + (i & 1) * STAGE_B;
#pragma unroll
        for (int ks = 0; ks < 4; ks++) {
            const int cb = ks * 32 + ((lane >> 4) << 4);
            uint32_t ah[4][4], al[4][4], wh[2][4], wl[2][4];
#pragma unroll
            for (int mi = 0; mi < 4; mi++) {
                int r = warp_m * 64 + mi * 16 + (lane & 15);
                uint32_t boff = r * 128 + cb;
                uint32_t sw = boff ^ ((boff >> 3) & 0x70);
                ldsm_x4(ah[mi], st + sw);
                ldsm_x4(al[mi], st + TILE_B + sw);
            }
#pragma unroll
            for (int np = 0; np < 2; np++) {
                int r = warp_n * 32 + np * 16 + (lane & 15);
                uint32_t boff = r * 128 + cb;
                uint32_t sw = boff ^ ((boff >> 3) & 0x70);
                ldsm_x4(wh[np], st + 2 * TILE_B + sw);
                ldsm_x4(wl[np], st + 3 * TILE_B + sw);
            }
#pragma unroll
            for (int mi = 0; mi < 4; mi++)
#pragma unroll
                for (int nj = 0; nj < 4; nj++) {
                    int np = nj >> 1, o = nj & 1;
                    mma_bf16(acc[mi][nj], ah[mi], wh[np][o], wh[np][o + 2]);
                    mma_bf16(acc[mi][nj], ah[mi], wl[np][o], wl[np][o + 2]);
                    mma_bf16(acc[mi][nj], al[mi], wh[np][o], wh[np][o + 2]);
                }
        }
        __syncthreads();
    }

    const int r0 = lane >> 2, c0 = (lane & 3) * 2;
#pragma unroll
    for (int mi = 0; mi < 4; mi++) {
#pragma unroll
        for (int nj = 0; nj < 4; nj++) {
            int row = bm + warp_m * 64 + mi * 16 + r0;
            int col = bn + warp_n * 32 + nj * 8 + c0;
            float2 b2 = *(const float2*)&bias[col];
            float v0 = (acc[mi][nj][0] + b2.x) * scale;
            float v1 = (acc[mi][nj][1] + b2.y) * scale;
            float v2 = (acc[mi][nj][2] + b2.x) * scale;
            float v3 = (acc[mi][nj][3] + b2.y) * scale;
            if (Chi) {
                __nv_bfloat162 h0, h1;
                uint32_t u0 = pack_hi(v0, v1, h0), u1 = pack_hi(v2, v3, h1);
                uint32_t l0 = pack_lo(v0, v1, h0), l1 = pack_lo(v2, v3, h1);
                *(uint32_t*)&Chi[(size_t)row * DMODEL + col] = u0;
                *(uint32_t*)&Clo[(size_t)row * DMODEL + col] = l0;
                *(uint32_t*)&Chi[(size_t)(row + 8) * DMODEL + col] = u1;
                *(uint32_t*)&Clo[(size_t)(row + 8) * DMODEL + col] = l1;
            } else {
                *(float2*)&C[(size_t)row * DMODEL + col] = make_float2(v0, v1);
                *(float2*)&C[(size_t)(row + 8) * DMODEL + col] = make_float2(v2, v3);
            }
        }
    }
}

// ---------------- flash attention on mma.sync, no-max softmax ---------------
// Q carries scale 0.125*log2(e); p = 2^(s + bias), bias in {0, -1e9}.
// Per-thread l partial sums; single reduction at the end. Mask bias staged
// through smem (coalesced cp.async) and read via ldmatrix (C-frag layout).
#define FA_STAGE 49152   // Khi,Klo,Vhi,Vlo (8KB each) + bias tile (16KB)
#define FA_SMEM  (2 * FA_STAGE)

__global__ __launch_bounds__(256, 1) void flash_attn_mma(
    const __nv_bfloat16* __restrict__ Qhi, const __nv_bfloat16* __restrict__ Qlo,
    const __nv_bfloat16* __restrict__ Khi, const __nv_bfloat16* __restrict__ Klo,
    const __nv_bfloat16* __restrict__ Vhi, const __nv_bfloat16* __restrict__ Vlo,
    const __nv_bfloat16* __restrict__ bias,
    __nv_bfloat16* __restrict__ Ahi, __nv_bfloat16* __restrict__ Alo)
{
    extern __shared__ __align__(1024) char smem[];
    const uint32_t sb = smem_u32(smem);
    const int tid = threadIdx.x, wid = tid >> 5, lane = tid & 31;
    const int q0 = blockIdx.x * 128, h = blockIdx.y, b = blockIdx.z;

    const size_t tok0 = (size_t)b * SLEN;
    const size_t hoff = (size_t)h * DKH;
    const int qr = q0 + wid * 16 + (lane >> 2);

    // Q fragments (A-frags over d), 4 k16 steps, hi/lo
    uint32_t qh[4][4], ql[4][4];
    {
        const size_t b0 = (tok0 + qr) * DMODEL + hoff;
        const size_t b1 = (tok0 + qr + 8) * DMODEL + hoff;
#pragma unroll
        for (int t = 0; t < 4; t++) {
            int c = t * 16 + 2 * (lane & 3);
            qh[t][0] = *(const uint32_t*)&Qhi[b0 + c];
            qh[t][1] = *(const uint32_t*)&Qhi[b1 + c];
            qh[t][2] = *(const uint32_t*)&Qhi[b0 + c + 8];
            qh[t][3] = *(const uint32_t*)&Qhi[b1 + c + 8];
            ql[t][0] = *(const uint32_t*)&Qlo[b0 + c];
            ql[t][1] = *(const uint32_t*)&Qlo[b1 + c];
            ql[t][2] = *(const uint32_t*)&Qlo[b0 + c + 8];
            ql[t][3] = *(const uint32_t*)&Qlo[b1 + c + 8];
        }
    }

    const __nv_bfloat16* srcs[4] = {
        Khi + tok0 * DMODEL + hoff, Klo + tok0 * DMODEL + hoff,
        Vhi + tok0 * DMODEL + hoff, Vlo + tok0 * DMODEL + hoff };
    const __nv_bfloat16* brow = bias + (tok0 + q0) * SLEN;

    auto load_kv = [&](int blk, int stage) {
        const int k0 = blk * 64;
        const uint32_t st = sb + stage * FA_STAGE;
#pragma unroll
        for (int i = 0; i < 8; i++) {
            int idx = tid + i * 256;
            int a = idx >> 9, r = (idx >> 3) & 63, c8 = idx & 7;
            uint32_t boff = r * 128 + c8 * 16;
            uint32_t sw = boff ^ ((boff >> 3) & 0x70);
            const void* g = srcs[a] + (size_t)(k0 + r) * DMODEL + c8 * 8;
            asm volatile("cp.async.cg.shared.global [%0], [%1], 16;"
                         :: "r"(st + a * 8192 + sw), "l"(g));
        }
        // mask-bias tile: 128 q-rows x 64 k-cols bf16, coalesced 128B rows
#pragma unroll
        for (int i = 0; i < 4; i++) {
            int idx = tid + i * 256;
            int r = idx >> 3, c8 = idx & 7;
            uint32_t boff = r * 128 + c8 * 16;
            uint32_t sw = boff ^ ((boff >> 3) & 0x70);
            const void* g = brow + (size_t)r * SLEN + k0 + c8 * 8;
            asm volatile("cp.async.cg.shared.global [%0], [%1], 16;"
                         :: "r"(st + 32768 + sw), "l"(g));
        }
        asm volatile("cp.async.commit_group;" ::: "memory");
    };

    float l[2] = { 0.f, 0.f };
    float o[8][4];
#pragma unroll
    for (int j = 0; j < 8; j++)
#pragma unroll
        for (int e = 0; e < 4; e++) o[j][e] = 0.f;

    load_kv(0, 0);

    for (int blk = 0; blk < SLEN / 64; blk++) {
        if (blk + 1 < SLEN / 64) {
            load_kv(blk + 1, (blk + 1) & 1);
            asm volatile("cp.async.wait_group 1;" ::: "memory");
        } else {
            asm volatile("cp.async.wait_group 0;" ::: "memory");
        }
        __syncthreads();
        const uint32_t st = sb + (blk & 1) * FA_STAGE;

        // ---- scores S = (Q * 0.125*log2e) K^T ----
        float S[8][4];
#pragma unroll
        for (int j = 0; j < 8; j++)
#pragma unroll
            for (int e = 0; e < 4; e++) S[j][e] = 0.f;

#pragma unroll
        for (int t = 0; t < 4; t++) {
            const int cb = t * 32 + ((lane >> 4) << 4);
#pragma unroll
            for (int np = 0; np < 4; np++) {
                int r = np * 16 + (lane & 15);
                uint32_t boff = r * 128 + cb;
                uint32_t sw = boff ^ ((boff >> 3) & 0x70);
                uint32_t kh[4], kl[4];
                ldsm_x4(kh, st + sw);
                ldsm_x4(kl, st + 8192 + sw);
#pragma unroll
                for (int o2 = 0; o2 < 2; o2++) {
                    int j = np * 2 + o2;
                    mma_bf16(S[j], qh[t], kh[o2], kh[o2 + 2]);
                    mma_bf16(S[j], qh[t], kl[o2], kl[o2 + 2]);
                    mma_bf16(S[j], ql[t], kh[o2], kh[o2 + 2]);
                }
            }
        }

        // ---- mask bias add (ldmatrix in C-frag layout) + exp2 + l accum ----
#pragma unroll
        for (int j2 = 0; j2 < 4; j2++) {
            uint32_t bf[4];
            int rr = wid * 16 + ((lane >> 3) & 1) * 8 + (lane & 7);
            int cc = (j2 * 2 + (lane >> 4)) * 16;
            uint32_t boff = rr * 128 + cc;
            uint32_t sw = boff ^ ((boff >> 3) & 0x70);
            ldsm_x4(bf, st + 32768 + sw);
            float2 f;
            f = __bfloat1622float2(*(__nv_bfloat162*)&bf[0]);
            S[2 * j2][0] += f.x; S[2 * j2][1] += f.y;
            f = __bfloat1622float2(*(__nv_bfloat162*)&bf[1]);
            S[2 * j2][2] += f.x; S[2 * j2][3] += f.y;
            f = __bfloat1622float2(*(__nv_bfloat162*)&bf[2]);
            S[2 * j2 + 1][0] += f.x; S[2 * j2 + 1][1] += f.y;
            f = __bfloat1622float2(*(__nv_bfloat162*)&bf[3]);
            S[2 * j2 + 1][2] += f.x; S[2 * j2 + 1][3] += f.y;
        }
#pragma unroll
        for (int j = 0; j < 8; j++) {
            S[j][0] = ex2(S[j][0]); S[j][1] = ex2(S[j][1]);
            S[j][2] = ex2(S[j][2]); S[j][3] = ex2(S[j][3]);
            l[0] += S[j][0] + S[j][1];
            l[1] += S[j][2] + S[j][3];
        }

        // ---- O += P V  (P from score frags, split hi/lo in registers) ----
#pragma unroll
        for (int t = 0; t < 4; t++) {
            uint32_t ph[4], pl[4];
            {
                __nv_bfloat162 h2;
                ph[0] = pack_hi(S[2 * t][0], S[2 * t][1], h2);
                pl[0] = pack_lo(S[2 * t][0], S[2 * t][1], h2);
                ph[1] = pack_hi(S[2 * t][2], S[2 * t][3], h2);
                pl[1] = pack_lo(S[2 * t][2], S[2 * t][3], h2);
                ph[2] = pack_hi(S[2 * t + 1][0], S[2 * t + 1][1], h2);
                pl[2] = pack_lo(S[2 * t + 1][0], S[2 * t + 1][1], h2);
                ph[3] = pack_hi(S[2 * t + 1][2], S[2 * t + 1][3], h2);
                pl[3] = pack_lo(S[2 * t + 1][2], S[2 * t + 1][3], h2);
            }
            const int vkey = t * 16 + ((lane >> 3) & 1) * 8 + (lane & 7);
#pragma unroll
            for (int g = 0; g < 4; g++) {
                int dcol = g * 16 + ((lane >> 4) & 1) * 8;
                uint32_t boff = vkey * 128 + dcol * 2;
                uint32_t sw = boff ^ ((boff >> 3) & 0x70);
                uint32_t vh[4], vl[4];
                ldsm_x4_t(vh, st + 16384 + sw);
                ldsm_x4_t(vl, st + 24576 + sw);
#pragma unroll
                for (int o2 = 0; o2 < 2; o2++) {
                    int j = g * 2 + o2;
                    mma_bf16(o[j], ph, vh[o2 * 2], vh[o2 * 2 + 1]);
                    mma_bf16(o[j], ph, vl[o2 * 2], vl[o2 * 2 + 1]);
                    mma_bf16(o[j], pl, vh[o2 * 2], vh[o2 * 2 + 1]);
                }
            }
        }
        __syncthreads();   // stage fully consumed before next-iter load overwrites
    }

    // ---- final l reduction across the quad, normalize, write A hi/lo ----
    l[0] += __shfl_xor_sync(0xffffffffu, l[0], 1);
    l[0] += __shfl_xor_sync(0xffffffffu, l[0], 2);
    l[1] += __shfl_xor_sync(0xffffffffu, l[1], 1);
    l[1] += __shfl_xor_sync(0xffffffffu, l[1], 2);
    const float i0 = 1.f / l[0], i1 = 1.f / l[1];
#pragma unroll
    for (int j = 0; j < 8; j++) {
        int c = j * 8 + 2 * (lane & 3);
        size_t a0 = (tok0 + qr) * DMODEL + hoff + c;
        size_t a1 = (tok0 + qr + 8) * DMODEL + hoff + c;
        __nv_bfloat162 h2;
        float f0 = o[j][0] * i0, f1 = o[j][1] * i0;
        uint32_t u = pack_hi(f0, f1, h2), v = pack_lo(f0, f1, h2);
        *(uint32_t*)&Ahi[a0] = u; *(uint32_t*)&Alo[a0] = v;
        f0 = o[j][2] * i1; f1 = o[j][3] * i1;
        u = pack_hi(f0, f1, h2); v = pack_lo(f0, f1, h2);
        *(uint32_t*)&Ahi[a1] = u; *(uint32_t*)&Alo[a1] = v;
    }
}

// ---------------- launcher ---------------------------------------------------
extern "C" void kernel_launch(void* const* d_in, const int* in_sizes, int n_in,
                              void* d_out, int out_size)
{
    const float* query = (const float*)d_in[0];
    const float* key   = (const float*)d_in[1];
    const float* value = (const float*)d_in[2];
    const int*   mask  = (const int*)d_in[3];
    const float* Wq    = (const float*)d_in[4];
    const float* bq    = (const float*)d_in[5];
    const float* Wk    = (const float*)d_in[6];
    const float* bk    = (const float*)d_in[7];
    const float* Wv    = (const float*)d_in[8];
    const float* bv    = (const float*)d_in[9];
    const float* Wo    = (const float*)d_in[10];
    const float* bo    = (const float*)d_in[11];
    float* out = (float*)d_out;

    __nv_bfloat16 *xhi, *xlo, *qhi, *qlo, *khi, *klo, *vhi, *vlo, *ahi, *alo, *bb;
    __nv_bfloat16 *wh[4], *wl[4];
    cudaGetSymbolAddress((void**)&xhi, g_xhi);
    cudaGetSymbolAddress((void**)&xlo, g_xlo);
    cudaGetSymbolAddress((void**)&qhi, g_qhi);
    cudaGetSymbolAddress((void**)&qlo, g_qlo);
    cudaGetSymbolAddress((void**)&khi, g_khi);
    cudaGetSymbolAddress((void**)&klo, g_klo);
    cudaGetSymbolAddress((void**)&vhi, g_vhi);
    cudaGetSymbolAddress((void**)&vlo, g_vlo);
    cudaGetSymbolAddress((void**)&ahi, g_ahi);
    cudaGetSymbolAddress((void**)&alo, g_alo);
    cudaGetSymbolAddress((void**)&bb,  g_bias);
    {
        __nv_bfloat16 *p;
        cudaGetSymbolAddress((void**)&p, g_wh);
        for (int i = 0; i < 4; i++) wh[i] = p + (size_t)i * DMODEL * DMODEL;
        cudaGetSymbolAddress((void**)&p, g_wl);
        for (int i = 0; i < 4; i++) wl[i] = p + (size_t)i * DMODEL * DMODEL;
    }

    cudaFuncSetAttribute(gemm_mma, cudaFuncAttributeMaxDynamicSharedMemorySize, GEMM_SMEM);
    cudaFuncSetAttribute(flash_attn_mma, cudaFuncAttributeMaxDynamicSharedMemorySize, FA_SMEM);

    const int nx4 = MROWS * DMODEL / 4;
    const int nw4 = DMODEL * DMODEL / 4;
    const int nb4 = BATCH * SLEN * SLEN / 4;
    dim3 gg(DMODEL / 128, MROWS / 128);

    mask_to_bias<<<nb4 / 256, 256>>>((const int4*)mask, (__nv_bfloat162*)bb, nb4);

    const float* Ws[4] = { Wq, Wk, Wv, Wo };
    for (int i = 0; i < 4; i++)
        split_f32<<<nw4 / 256, 256>>>((const float4*)Ws[i], (__nv_bfloat162*)wh[i],
                                      (__nv_bfloat162*)wl[i], nw4);

    // Q scale folds 1/sqrt(dk) * log2(e) so softmax uses raw ex2.
    const float QSCALE = 0.125f * 1.4426950408889634f;

    split_f32<<<nx4 / 256, 256>>>((const float4*)query, (__nv_bfloat162*)xhi,
                                  (__nv_bfloat162*)xlo, nx4);
    gemm_mma<<<gg, 256, GEMM_SMEM>>>(xhi, xlo, wh[0], wl[0], bq, nullptr, qhi, qlo, QSCALE);

    split_f32<<<nx4 / 256, 256>>>((const float4*)key, (__nv_bfloat162*)xhi,
                                  (__nv_bfloat162*)xlo, nx4);
    gemm_mma<<<gg, 256, GEMM_SMEM>>>(xhi, xlo, wh[1], wl[1], bk, nullptr, khi, klo, 1.f);

    split_f32<<<nx4 / 256, 256>>>((const float4*)value, (__nv_bfloat162*)xhi,
                                  (__nv_bfloat162*)xlo, nx4);
    gemm_mma<<<gg, 256, GEMM_SMEM>>>(xhi, xlo, wh[2], wl[2], bv, nullptr, vhi, vlo, 1.f);

    dim3 fg(SLEN / 128, NHEAD, BATCH);   // (16, 16, 2)
    flash_attn_mma<<<fg, 256, FA_SMEM>>>(qhi, qlo, khi, klo, vhi, vlo, bb, ahi, alo);

    gemm_mma<<<gg, 256, GEMM_SMEM>>>(ahi, alo, wh[3], wl[3], bo, out, nullptr, nullptr, 1.f);
}